// round 15
// baseline (speedup 1.0000x reference)
#include <cuda_runtime.h>
#include <cuda_bf16.h>
#include <cstdint>

#define BB 2
#define CC 64
#define CQ 16
#define DD 96
#define PP 9216                    // H*W
#define PDSTRIDE (PP*DD)           // per-channel stride in x
#define CPD (CC*PDSTRIDE)          // per-batch stride in x
#define PCHUNK 64                  // p per block (energy)
#define OPB 32                     // p per block (out)

typedef unsigned long long u64;
typedef unsigned int u32;

__device__ double g_energy[BB*DD*DD];
__device__ int    g_nnz [BB*DD];
__device__ int    g_eidx[BB*DD*DD];
__device__ float  g_aval[BB*DD*DD];

// ---- mma.sync bf16 ----
__device__ __forceinline__ void mma16816(float* d, const u32* a, u32 b0, u32 b1) {
    asm volatile(
        "mma.sync.aligned.m16n8k16.row.col.f32.bf16.bf16.f32 "
        "{%0,%1,%2,%3},{%4,%5,%6,%7},{%8,%9},{%0,%1,%2,%3};"
        : "+f"(d[0]), "+f"(d[1]), "+f"(d[2]), "+f"(d[3])
        : "r"(a[0]), "r"(a[1]), "r"(a[2]), "r"(a[3]), "r"(b0), "r"(b1));
}
__device__ __forceinline__ void splitbf(float v, __nv_bfloat16& h, __nv_bfloat16& l) {
    h = __float2bfloat16(v);
    l = __float2bfloat16(v - __bfloat162float(h));
}
__device__ __forceinline__ u32 pkbf(__nv_bfloat16 lo16, __nv_bfloat16 hi16) {
    return ((u32)__bfloat16_as_ushort(hi16) << 16) | (u32)__bfloat16_as_ushort(lo16);
}

// ===========================================================================
// Kernel A v2 (full tensor): per p,
//   GEMM1': T[d, cq32] = X^T(96x64) * Wqk^T(64x32) + bias   (split-3 bf16)
//   GEMM2 : energy[d,e] += Q^T(96x16) K(16x96)               (split-3 bf16)
// Q/K round-trip through smem as split-bf16 [d][cq-pair]; energy accumulates
// in fp32 fragments over all 64 p, flushed once via fp64 atomics.
// ===========================================================================
#define EXW 33                     // X word stride ([d][c-pair])
#define EWW 33                     // Wqk word stride ([cq][c-pair])
#define EQW 9                      // Q/K word stride ([d][cq-pair])
#define U_XH 0
#define U_XL (U_XH + DD*EXW)       // 3168
#define U_WH (U_XL + DD*EXW)       // 6336
#define U_WL (U_WH + 32*EWW)       // 7392
#define U_QH (U_WL + 32*EWW)       // 8448
#define U_QL (U_QH + DD*EQW)       // 9312
#define U_KH (U_QL + DD*EQW)       // 10176
#define U_KL (U_KH + DD*EQW)       // 11040
#define E_WORDS (U_KL + DD*EQW)    // 11904 words = 47616 B

__global__ void __launch_bounds__(256, 2) energy_k(
    const float* __restrict__ x,
    const float* __restrict__ Wq, const float* __restrict__ bq,
    const float* __restrict__ Wk, const float* __restrict__ bk)
{
    extern __shared__ __align__(16) u32 eum[];
    u32* sXh = eum + U_XH;
    u32* sXl = eum + U_XL;
    u32* sWh = eum + U_WH;
    u32* sWl = eum + U_WL;
    u32* sQh = eum + U_QH;
    u32* sQl = eum + U_QL;
    u32* sKh = eum + U_KH;
    u32* sKl = eum + U_KL;

    const int t    = threadIdx.x;
    const int b    = blockIdx.y;
    const int p0   = blockIdx.x * PCHUNK;
    const int lane = t & 31;
    const int wrp  = t >> 5;
    const int lg   = lane >> 2;
    const int tc   = lane & 3;

    // ---- Wqk combined split-bf16 table [cq32][c-pair32] (built once) ----
    for (int i = t; i < 32*32; i += 256) {
        const int row = i >> 5, wp = i & 31;
        const int c0 = 2*wp;
        const float v0 = (row < 16) ? Wq[row*CC + c0]     : Wk[(row-16)*CC + c0];
        const float v1 = (row < 16) ? Wq[row*CC + c0 + 1] : Wk[(row-16)*CC + c0 + 1];
        __nv_bfloat16 h0, l0, h1, l1;
        splitbf(v0, h0, l0); splitbf(v1, h1, l1);
        sWh[row*EWW + wp] = pkbf(h0, h1);
        sWl[row*EWW + wp] = pkbf(l0, l1);
    }

    // ---- per-tile GEMM1 bias (col cq = nt*8 + 2tc (+1)) ----
    float bias0[3], bias1[3];
    #pragma unroll
    for (int i = 0; i < 3; ++i) {
        const int nt1 = (3*wrp + i) & 3;
        const float* bb = (nt1 < 2) ? bq : bk;
        const int idx = (nt1 & 1)*8 + 2*tc;
        bias0[i] = bb[idx];
        bias1[i] = bb[idx + 1];
    }

    // ---- persistent energy fragments: 9 tiles x 4 ----
    float eacc[9][4];
    #pragma unroll
    for (int i = 0; i < 9; ++i)
        #pragma unroll
        for (int j = 0; j < 4; ++j) eacc[i][j] = 0.f;

    const float* xb = x + (size_t)b * CPD;

    // slab loader: li = c-pair (0..31), j0 = d block of 12
    const int li = t >> 3;
    const int j0 = (t & 7) * 12;

    float4 r4[6];
    #define ELDG(P) {                                                           \
        const float* s0 = xb + (size_t)(2*li) * PDSTRIDE + (size_t)(P) * DD + j0; \
        const float* s1 = s0 + PDSTRIDE;                                        \
        _Pragma("unroll")                                                       \
        for (int q = 0; q < 3; ++q) {                                           \
            r4[q]   = *reinterpret_cast<const float4*>(s0 + 4*q);               \
            r4[3+q] = *reinterpret_cast<const float4*>(s1 + 4*q); } }
    #define ESTS() {                                                            \
        const float* f0 = reinterpret_cast<const float*>(r4);                   \
        const float* f1 = f0 + 12;                                              \
        _Pragma("unroll")                                                       \
        for (int k = 0; k < 12; ++k) {                                          \
            __nv_bfloat16 h0, l0, h1, l1;                                       \
            splitbf(f0[k], h0, l0);                                             \
            splitbf(f1[k], h1, l1);                                             \
            sXh[(j0 + k)*EXW + li] = pkbf(h0, h1);                              \
            sXl[(j0 + k)*EXW + li] = pkbf(l0, l1); } }

    ELDG(p0);
    ESTS();
    __syncthreads();                     // Wqk table + X(p0) visible

    for (int pp = 0; pp < PCHUNK; ++pp) {
        // ---- phase A: GEMM1' (3 tiles/warp), D = X^T Wqk^T + bias ----
        float dacc[3][4];
        #pragma unroll
        for (int i = 0; i < 3; ++i) {
            dacc[i][0] = bias0[i]; dacc[i][1] = bias1[i];
            dacc[i][2] = bias0[i]; dacc[i][3] = bias1[i];
        }
        #pragma unroll
        for (int i = 0; i < 3; ++i) {
            const int t1 = 3*wrp + i;
            const int mt1 = t1 >> 2, nt1 = t1 & 3;
            const int r0 = (mt1*16 + lg) * EXW;
            const int r1 = r0 + 8*EXW;
            const int bw = (nt1*8 + lg) * EWW;
            #pragma unroll
            for (int kt = 0; kt < 4; ++kt) {
                const int ac = kt*8 + tc;
                u32 axh[4] = { sXh[r0 + ac], sXh[r1 + ac],
                               sXh[r0 + ac + 4], sXh[r1 + ac + 4] };
                u32 axl[4] = { sXl[r0 + ac], sXl[r1 + ac],
                               sXl[r0 + ac + 4], sXl[r1 + ac + 4] };
                const u32 b0h = sWh[bw + ac], b1h = sWh[bw + ac + 4];
                const u32 b0l = sWl[bw + ac], b1l = sWl[bw + ac + 4];
                mma16816(dacc[i], axh, b0h, b1h);
                mma16816(dacc[i], axl, b0h, b1h);
                mma16816(dacc[i], axh, b0l, b1l);
            }
        }
        // epilogue: D -> split-bf16 Q/K [d][cq-pair]
        #pragma unroll
        for (int i = 0; i < 3; ++i) {
            const int t1 = 3*wrp + i;
            const int mt1 = t1 >> 2, nt1 = t1 & 3;
            u32* dsth = (nt1 < 2) ? sQh : sKh;
            u32* dstl = (nt1 < 2) ? sQl : sKl;
            const int wc = (nt1 & 1)*4 + tc;
            const int d0 = mt1*16 + lg;
            __nv_bfloat16 h0, l0, h1, l1;
            splitbf(dacc[i][0], h0, l0);
            splitbf(dacc[i][1], h1, l1);
            dsth[d0*EQW + wc] = pkbf(h0, h1);
            dstl[d0*EQW + wc] = pkbf(l0, l1);
            splitbf(dacc[i][2], h0, l0);
            splitbf(dacc[i][3], h1, l1);
            dsth[(d0 + 8)*EQW + wc] = pkbf(h0, h1);
            dstl[(d0 + 8)*EQW + wc] = pkbf(l0, l1);
        }
        __syncthreads();                 // Q/K visible; X(pp) consumed

        // ---- phase B: GEMM2 energy accum (9 tiles/warp) + X(pp+1) refill ----
        if (pp + 1 < PCHUNK) ELDG(p0 + pp + 1);

        #pragma unroll
        for (int i = 0; i < 9; ++i) {
            const int t2 = 9*wrp + i;
            const int mt2 = t2 / 12, nt2 = t2 % 12;
            const int r0 = (mt2*16 + lg) * EQW;
            const int r1 = r0 + 8*EQW;
            u32 qh[4] = { sQh[r0 + tc], sQh[r1 + tc],
                          sQh[r0 + tc + 4], sQh[r1 + tc + 4] };
            u32 ql[4] = { sQl[r0 + tc], sQl[r1 + tc],
                          sQl[r0 + tc + 4], sQl[r1 + tc + 4] };
            const int kb = (nt2*8 + lg) * EQW;
            const u32 kh0 = sKh[kb + tc], kh1 = sKh[kb + tc + 4];
            const u32 kl0 = sKl[kb + tc], kl1 = sKl[kb + tc + 4];
            mma16816(eacc[i], qh, kh0, kh1);
            mma16816(eacc[i], ql, kh0, kh1);
            mma16816(eacc[i], qh, kl0, kl1);
        }

        if (pp + 1 < PCHUNK) ESTS();
        __syncthreads();                 // next X visible; Q/K reusable
    }

    // ---- flush: fp64 atomics ----
    const size_t eb = (size_t)b * DD * DD;
    #pragma unroll
    for (int i = 0; i < 9; ++i) {
        const int t2 = 9*wrp + i;
        const int mt2 = t2 / 12, nt2 = t2 % 12;
        const int r0 = mt2*16 + lg;
        const int e0 = nt2*8 + 2*tc;
        atomicAdd(&g_energy[eb + (size_t)r0*DD + e0],        (double)eacc[i][0]);
        atomicAdd(&g_energy[eb + (size_t)r0*DD + e0 + 1],    (double)eacc[i][1]);
        atomicAdd(&g_energy[eb + (size_t)(r0+8)*DD + e0],    (double)eacc[i][2]);
        atomicAdd(&g_energy[eb + (size_t)(r0+8)*DD + e0 + 1],(double)eacc[i][3]);
    }
    #undef ELDG
    #undef ESTS
}

// ===========================================================================
// Kernel B: row softmax + compaction (a > 1e-8). One warp per (b,d) row.
// ===========================================================================
#define ATHRESH 1e-8f

__global__ void __launch_bounds__(128) softmax_k()
{
    const int w    = (blockIdx.x * blockDim.x + threadIdx.x) >> 5;
    const int lane = threadIdx.x & 31;
    if (w >= BB*DD) return;

    const double* er = g_energy + (size_t)w * DD;
    float v0 = (float)er[lane];
    float v1 = (float)er[lane + 32];
    float v2 = (float)er[lane + 64];

    float m = fmaxf(v0, fmaxf(v1, v2));
    #pragma unroll
    for (int o = 16; o > 0; o >>= 1) m = fmaxf(m, __shfl_xor_sync(0xffffffffu, m, o));

    float e0 = expf(v0 - m), e1 = expf(v1 - m), e2 = expf(v2 - m);
    float s = e0 + e1 + e2;
    #pragma unroll
    for (int o = 16; o > 0; o >>= 1) s += __shfl_xor_sync(0xffffffffu, s, o);

    const float inv = 1.0f / s;
    const float a[3] = { e0 * inv, e1 * inv, e2 * inv };

    int* ei = g_eidx + (size_t)w * DD;
    float* av = g_aval + (size_t)w * DD;
    const unsigned lmask = (1u << lane) - 1u;
    int base = 0;
    #pragma unroll
    for (int sct = 0; sct < 3; ++sct) {
        const bool keep = a[sct] > ATHRESH;
        const unsigned mask = __ballot_sync(0xffffffffu, keep);
        if (keep) {
            const int idx = base + __popc(mask & lmask);
            ei[idx] = lane + 32*sct;
            av[idx] = a[sct];
        }
        base += __popc(mask);
    }
    if (lane == 0) g_nnz[w] = base;
}

// ===========================================================================
// Kernel C (R14 verbatim): gather-before-GEMM + mma.sync split-3 bf16.
// ===========================================================================
#define XBW 37
#define SXS 100
#define Y_SX 0
#define Y_BH (Y_SX + 2*CC*SXS)
#define Y_BL (Y_BH + DD*XBW)
#define Y_FLOATS (Y_BL + DD*XBW)

__global__ void __launch_bounds__(256, 2) outy_k(
    const float* __restrict__ x, const float* __restrict__ Wv,
    const float* __restrict__ bv, const float* __restrict__ gamma,
    float* __restrict__ out)
{
    extern __shared__ __align__(16) float osm[];
    float* sX0 = osm + Y_SX;
    u32*   sBh = (u32*)(osm + Y_BH);
    u32*   sBl = (u32*)(osm + Y_BL);

    const int t    = threadIdx.x;
    const int b    = blockIdx.y;
    const int p0   = blockIdx.x * OPB;
    const int lane = t & 31;
    const int wrp  = t >> 5;
    const int lg   = lane >> 2;
    const int tc   = lane & 3;
    const int mt   = wrp >> 1;
    const int nb   = (wrp & 1) * 48;

    const float gam = gamma[0];

    u32 ah[4][4], al[4][4];
    {
        const int r0 = mt*16 + lg, r1 = r0 + 8;
        #pragma unroll
        for (int kt = 0; kt < 4; ++kt) {
            const int c0 = kt*16 + 2*tc;
            const float w00 = Wv[r0*CC + c0],     w01 = Wv[r0*CC + c0 + 1];
            const float w10 = Wv[r1*CC + c0],     w11 = Wv[r1*CC + c0 + 1];
            const float w02 = Wv[r0*CC + c0 + 8], w03 = Wv[r0*CC + c0 + 9];
            const float w12 = Wv[r1*CC + c0 + 8], w13 = Wv[r1*CC + c0 + 9];
            __nv_bfloat16 h, l, h2, l2;
            splitbf(w00, h, l); splitbf(w01, h2, l2);
            ah[kt][0] = pkbf(h, h2); al[kt][0] = pkbf(l, l2);
            splitbf(w10, h, l); splitbf(w11, h2, l2);
            ah[kt][1] = pkbf(h, h2); al[kt][1] = pkbf(l, l2);
            splitbf(w02, h, l); splitbf(w03, h2, l2);
            ah[kt][2] = pkbf(h, h2); al[kt][2] = pkbf(l, l2);
            splitbf(w12, h, l); splitbf(w13, h2, l2);
            ah[kt][3] = pkbf(h, h2); al[kt][3] = pkbf(l, l2);
        }
    }
    const float gbA = gam * bv[mt*16 + lg];
    const float gbB = gam * bv[mt*16 + lg + 8];

    int   nL[3], e0L[3], e1L[3];
    float ga0L[3], ga1L[3];
    #pragma unroll
    for (int dd = 0; dd < 3; ++dd) {
        const int d = lane + 32*dd;
        const int w = b*DD + d;
        const int n = g_nnz[w];
        nL[dd]  = n;
        e0L[dd] = g_eidx[(size_t)w*DD];
        ga0L[dd] = gam * g_aval[(size_t)w*DD];
        e1L[dd] = (n > 1) ? g_eidx[(size_t)w*DD + 1] : 0;
        ga1L[dd] = (n > 1) ? gam * g_aval[(size_t)w*DD + 1] : 0.f;
    }

    const float* xb = x   + (size_t)b * CPD;
    float*       ob = out + (size_t)b * CPD;

    const int li = t >> 3;
    const int j0 = (t & 7) * 12;

    float4 r4[6];
    #define LDG1(P) {                                                           \
        const float* s0 = xb + (size_t)(2*li)   * PDSTRIDE + (size_t)(P) * DD + j0; \
        const float* s1 = xb + (size_t)(2*li+1) * PDSTRIDE + (size_t)(P) * DD + j0; \
        _Pragma("unroll")                                                       \
        for (int q = 0; q < 3; ++q) {                                           \
            r4[q]   = *reinterpret_cast<const float4*>(s0 + 4*q);               \
            r4[3+q] = *reinterpret_cast<const float4*>(s1 + 4*q); } }
    #define STS1(BUF) {                                                         \
        _Pragma("unroll")                                                       \
        for (int q = 0; q < 3; ++q) {                                           \
            *reinterpret_cast<float4*>(&(BUF)[(2*li)*SXS   + j0 + 4*q]) = r4[q]; \
            *reinterpret_cast<float4*>(&(BUF)[(2*li+1)*SXS + j0 + 4*q]) = r4[3+q]; } }

    LDG1(p0);
    STS1(sX0);
    __syncthreads();

    for (int pp = 0; pp < OPB; ++pp) {
        const int p = p0 + pp;
        const float* sX = sX0 + (pp & 1) * (CC*SXS);

        if (pp + 1 < OPB) LDG1(p + 1);

        #pragma unroll
        for (int dd = 0; dd < 3; ++dd) {
            const int d  = lane + 32*dd;
            const int e0 = e0L[dd], e1 = e1L[dd];
            const float a0 = ga0L[dd], a1 = ga1L[dd];
            #pragma unroll
            for (int w = 0; w < 4; ++w) {
                const int c2p = 4*wrp + w;
                const int c2  = 2*c2p;
                float ylo = fmaf(a0, sX[c2*SXS + e0],     a1 * sX[c2*SXS + e1]);
                float yhi = fmaf(a0, sX[(c2+1)*SXS + e0], a1 * sX[(c2+1)*SXS + e1]);
                if (nL[dd] > 2) {
                    const size_t wr = (size_t)(b*DD + d) * DD;
                    for (int k = 2; k < nL[dd]; ++k) {
                        const float ak = gam * g_aval[wr + k];
                        const int   ek = g_eidx[wr + k];
                        ylo = fmaf(ak, sX[c2*SXS + ek],     ylo);
                        yhi = fmaf(ak, sX[(c2+1)*SXS + ek], yhi);
                    }
                }
                __nv_bfloat16 h0, l0, h1, l1;
                splitbf(ylo, h0, l0);
                splitbf(yhi, h1, l1);
                sBh[d*XBW + c2p] = pkbf(h0, h1);
                sBl[d*XBW + c2p] = pkbf(l0, l1);
            }
        }
        __syncthreads();

        if (pp + 1 < OPB) STS1(sX0 + ((pp + 1) & 1) * (CC*SXS));

        float dacc[6][4];
        #pragma unroll
        for (int nt = 0; nt < 6; ++nt) {
            dacc[nt][0] = gbA; dacc[nt][1] = gbA;
            dacc[nt][2] = gbB; dacc[nt][3] = gbB;
        }
        #pragma unroll
        for (int nt = 0; nt < 6; ++nt) {
            const int db = nb + nt*8 + lg;
            #pragma unroll
            for (int kt = 0; kt < 4; ++kt) {
                const int wof = db*XBW + kt*8 + tc;
                const u32 b0h = sBh[wof], b1h = sBh[wof + 4];
                const u32 b0l = sBl[wof], b1l = sBl[wof + 4];
                mma16816(dacc[nt], ah[kt], b0h, b1h);
                mma16816(dacc[nt], al[kt], b0h, b1h);
                mma16816(dacc[nt], ah[kt], b0l, b1l);
            }
        }

        {
            const int r0 = mt*16 + lg, r1 = r0 + 8;
            float* o0 = ob + (size_t)r0 * PDSTRIDE + (size_t)p * DD;
            float* o1 = ob + (size_t)r1 * PDSTRIDE + (size_t)p * DD;
            #pragma unroll
            for (int nt = 0; nt < 6; ++nt) {
                const int ec = nb + nt*8 + 2*tc;
                const float2 xr0 = *reinterpret_cast<const float2*>(&sX[r0*SXS + ec]);
                const float2 xr1 = *reinterpret_cast<const float2*>(&sX[r1*SXS + ec]);
                float2 v0; v0.x = dacc[nt][0] + xr0.x; v0.y = dacc[nt][1] + xr0.y;
                float2 v1; v1.x = dacc[nt][2] + xr1.x; v1.y = dacc[nt][3] + xr1.y;
                *reinterpret_cast<float2*>(o0 + ec) = v0;
                *reinterpret_cast<float2*>(o1 + ec) = v1;
            }
        }
        __syncthreads();
    }
    #undef LDG1
    #undef STS1
}

// ---------------------------------------------------------------------------
extern "C" void kernel_launch(void* const* d_in, const int* in_sizes, int n_in,
                              void* d_out, int out_size)
{
    const float* x  = (const float*)d_in[0];
    const float* Wq = (const float*)d_in[1];
    const float* bq = (const float*)d_in[2];
    const float* Wk = (const float*)d_in[3];
    const float* bk = (const float*)d_in[4];
    const float* Wv = (const float*)d_in[5];
    const float* bv = (const float*)d_in[6];
    const float* gm = (const float*)d_in[7];
    float* out = (float*)d_out;

    void* eptr = nullptr;
    cudaGetSymbolAddress(&eptr, g_energy);
    cudaMemsetAsync(eptr, 0, sizeof(double)*BB*DD*DD, 0);

    cudaFuncSetAttribute(energy_k, cudaFuncAttributeMaxDynamicSharedMemorySize,
                         E_WORDS * (int)sizeof(u32));
    energy_k<<<dim3(PP/PCHUNK, BB), 256, E_WORDS*sizeof(u32)>>>(x, Wq, bq, Wk, bk);

    softmax_k<<<(BB*DD*32 + 127)/128, 128>>>();

    cudaFuncSetAttribute(outy_k, cudaFuncAttributeMaxDynamicSharedMemorySize,
                         Y_FLOATS * (int)sizeof(float));
    outy_k<<<dim3(PP/OPB, BB), 256, Y_FLOATS*sizeof(float)>>>(x, Wv, bv, gm, out);
}